// round 7
// baseline (speedup 1.0000x reference)
#include <cuda_runtime.h>
#include <float.h>
#include <math.h>

#define NB 16
#define NP 1024
#define NC 91
#define MAX_DET 100
#define SCORE_THRESH 0.05f
#define NMS_THRESH 0.5f
#define BBOX_CLIP 4.135166556742356f  /* log(1000/16) */
#define BK 128                        /* bucket capacity per (image,class) */
#define C_PARTS 64
#define C_THREADS 512

// ---------------- scratch (no allocations allowed) ----------------
__device__ float  g_scores[NB * NP];
__device__ int    g_labels[NB * NP];           // 0 if invalid, else 1..90
__device__ float4 g_boxes[NB * NP];

__device__ int    g_bcnt[NB * 91];             // bucket counts
__device__ float4 g_bbox[NB * 91 * BK];        // bucket boxes (raw clipped)
__device__ float  g_bsc [NB * 91 * BK];        // bucket scores
__device__ int    g_bidx[NB * 91 * BK];        // bucket original idx (0..1023)
__device__ int    g_maxc[NB];                  // per-image max coord (float bits)
__device__ int    g_M[NB];                     // kept count per image
__device__ unsigned long long g_klist[NB * NP];// kept keys per image (contiguous)

// ---------------- Kernel Z: reset counters ----------------
__global__ void zero_kernel() {
    int t = blockIdx.x * blockDim.x + threadIdx.x;
    if (t < NB * 91) g_bcnt[t] = 0;
    if (t < NB) { g_maxc[t] = 0; g_M[t] = 0; }
}

// ---------------- Kernel A: softmax-max/argmax + decode + clip + bucket ----------------
// One warp per proposal. Lanes cover classes {lane, lane+32, lane+64}.
__global__ void score_decode_kernel(const float* __restrict__ logits,
                                    const float* __restrict__ deltas,
                                    const float* __restrict__ props,
                                    const int*   __restrict__ imsz) {
    int gw   = (blockIdx.x * blockDim.x + threadIdx.x) >> 5;
    int lane = threadIdx.x & 31;
    if (gw >= NB * NP) return;

    const float* row = logits + (size_t)gw * NC;
    float l0 = row[lane];
    float l1 = row[lane + 32];
    bool  has2 = (lane < NC - 64);           // lane < 27
    float l2 = has2 ? row[lane + 64] : -FLT_MAX;

    // local argmax with first-index tie break
    float bv = l0; int bi = lane;
    if (l1 > bv) { bv = l1; bi = lane + 32; }
    if (l2 > bv) { bv = l2; bi = lane + 64; }
    #pragma unroll
    for (int o = 16; o; o >>= 1) {
        float ov = __shfl_down_sync(0xffffffffu, bv, o);
        int   oi = __shfl_down_sync(0xffffffffu, bi, o);
        if (ov > bv || (ov == bv && oi < bi)) { bv = ov; bi = oi; }
    }
    bv = __shfl_sync(0xffffffffu, bv, 0);
    bi = __shfl_sync(0xffffffffu, bi, 0);

    float s = expf(l0 - bv) + expf(l1 - bv) + (has2 ? expf(l2 - bv) : 0.0f);
    #pragma unroll
    for (int o = 16; o; o >>= 1) s += __shfl_down_sync(0xffffffffu, s, o);

    if (lane == 0) {
        float score = 1.0f / s;
        int label = bi;
        int b = gw / NP;
        int valid = (label > 0) && (score > SCORE_THRESH);

        const float* p = props + (size_t)gw * 4;
        float x1 = p[0], y1 = p[1], x2 = p[2], y2 = p[3];
        float w = x2 - x1, h = y2 - y1;
        float cx = x1 + 0.5f * w, cy = y1 + 0.5f * h;

        const float* dd = deltas + (size_t)gw * (NC * 4) + 4 * label;
        float dx = dd[0], dy = dd[1];
        float dw = fminf(dd[2], BBOX_CLIP), dh = fminf(dd[3], BBOX_CLIP);
        float pcx = dx * w + cx, pcy = dy * h + cy;
        float pw = expf(dw) * w, ph = expf(dh) * h;
        float bx1 = pcx - 0.5f * pw, by1 = pcy - 0.5f * ph;
        float bx2 = pcx + 0.5f * pw, by2 = pcy + 0.5f * ph;

        float hb = (float)imsz[b * 2 + 0];
        float wb = (float)imsz[b * 2 + 1];
        bx1 = fminf(fmaxf(bx1, 0.0f), wb);
        by1 = fminf(fmaxf(by1, 0.0f), hb);
        bx2 = fminf(fmaxf(bx2, 0.0f), wb);
        by2 = fminf(fmaxf(by2, 0.0f), hb);

        g_boxes[gw]  = make_float4(bx1, by1, bx2, by2);
        g_scores[gw] = score;
        g_labels[gw] = valid ? label : 0;

        if (valid) {
            // exact max over valid box coords (all >= 0, float bits monotone)
            float mc = fmaxf(fmaxf(bx1, by1), fmaxf(bx2, by2));
            atomicMax(&g_maxc[b], __float_as_int(mc));
            int bc = b * 91 + label;
            int p2 = atomicAdd(&g_bcnt[bc], 1);
            if (p2 < BK) {
                int slot = bc * BK + p2;
                g_bbox[slot] = make_float4(bx1, by1, bx2, by2);
                g_bsc[slot]  = score;
                g_bidx[slot] = gw - b * NP;
            }
        }
    }
}

// ---------------- Kernel B: NMS, one warp per (image, class), registers only ----
// Kept keys appended to the image's contiguous list with ONE atomic per warp.
__global__ __launch_bounds__(256) void nms_class_kernel() {
    int gwarp = (blockIdx.x * blockDim.x + threadIdx.x) >> 5;
    int lane  = threadIdx.x & 31;
    if (gwarp >= NB * 90) return;
    int b = gwarp / 90;
    int c = 1 + gwarp % 90;
    int bc = b * 91 + c;

    int n = g_bcnt[bc];
    if (n > BK) n = BK;
    if (n == 0) return;

    float K   = __int_as_float(g_maxc[b]) + 1.0f;
    float off = (float)c * K;    // label * (max_coord + 1), reference FP order

    float4 bxs[4]; float scs[4]; int idxs[4];
    unsigned alive = 0;
    #pragma unroll
    for (int j = 0; j < 4; ++j) {
        int e = j * 32 + lane;
        if (e < n) {
            float4 v = g_bbox[bc * BK + e];
            bxs[j] = make_float4(v.x + off, v.y + off, v.z + off, v.w + off);
            scs[j] = g_bsc[bc * BK + e];
            idxs[j] = g_bidx[bc * BK + e];
            alive |= (1u << j);
        } else {
            bxs[j] = make_float4(0.f, 0.f, 0.f, 0.f);
            scs[j] = 0.f; idxs[j] = 0;
        }
    }

    unsigned keptm = 0;
    while (true) {
        // per-lane best alive key: (~score_bits, orig_idx, slot)
        unsigned long long best = ~0ULL;
        #pragma unroll
        for (int j = 0; j < 4; ++j) {
            if (alive & (1u << j)) {
                unsigned long long k =
                    ((unsigned long long)(~__float_as_uint(scs[j])) << 20) |
                    ((unsigned long long)(unsigned)idxs[j] << 10) |
                    (unsigned long long)(unsigned)(j * 32 + lane);
                if (k < best) best = k;
            }
        }
        #pragma unroll
        for (int o = 16; o; o >>= 1) {
            unsigned long long ob = __shfl_xor_sync(0xffffffffu, best, o);
            if (ob < best) best = ob;
        }
        if (best == ~0ULL) break;

        int e   = (int)(best & 1023ULL);
        int js  = e >> 5;
        int src = e & 31;
        float4 own = (js == 0) ? bxs[0] : (js == 1) ? bxs[1] : (js == 2) ? bxs[2] : bxs[3];
        float4 A;
        A.x = __shfl_sync(0xffffffffu, own.x, src);
        A.y = __shfl_sync(0xffffffffu, own.y, src);
        A.z = __shfl_sync(0xffffffffu, own.z, src);
        A.w = __shfl_sync(0xffffffffu, own.w, src);
        if (lane == src) {
            alive &= ~(1u << js);
            keptm |= (1u << js);
        }
        float areaA = (A.z - A.x) * (A.w - A.y);

        #pragma unroll
        for (int j = 0; j < 4; ++j) {
            if (alive & (1u << j)) {
                float4 Bx = bxs[j];
                float areaB = (Bx.z - Bx.x) * (Bx.w - Bx.y);
                float ltx = fmaxf(A.x, Bx.x), lty = fmaxf(A.y, Bx.y);
                float rbx = fminf(A.z, Bx.z), rby = fminf(A.w, Bx.w);
                float wx = fmaxf(rbx - ltx, 0.0f), wy = fmaxf(rby - lty, 0.0f);
                float inter = wx * wy;
                float iou = inter / (areaA + areaB - inter + 1e-9f);
                if (iou > NMS_THRESH) alive &= ~(1u << j);
            }
        }
    }

    // single aggregated atomic per warp, ballot-prefixed positions
    int pref[4];
    int kc = 0;
    #pragma unroll
    for (int j = 0; j < 4; ++j) {
        bool kept = (keptm >> j) & 1u;
        unsigned bal = __ballot_sync(0xffffffffu, kept);
        pref[j] = kc + __popc(bal & ((1u << lane) - 1u));
        kc += __popc(bal);
    }
    int basep = 0;
    if (lane == 0 && kc > 0) basep = atomicAdd(&g_M[b], kc);
    basep = __shfl_sync(0xffffffffu, basep, 0);
    #pragma unroll
    for (int j = 0; j < 4; ++j) {
        if ((keptm >> j) & 1u) {
            g_klist[b * NP + basep + pref[j]] =
                ((unsigned long long)(~__float_as_uint(scs[j])) << 10) |
                (unsigned long long)(unsigned)idxs[j];
        }
    }
}

// ---------------- Kernel C: per-image top-100, one warp per entry ----------------
__global__ __launch_bounds__(C_THREADS) void topk_rank_kernel(float* __restrict__ out) {
    const int img  = blockIdx.x / C_PARTS;
    const int part = blockIdx.x % C_PARTS;
    const int t    = threadIdx.x;
    const int warp = t >> 5;
    const int lane = t & 31;

    __shared__ unsigned long long s_keys[NP];   // 8 KB

    int M = g_M[img];
    if (M > NP) M = NP;
    for (int i = t; i < M; i += C_THREADS)
        s_keys[i] = g_klist[img * NP + i];
    __syncthreads();

    float* boxes_out  = out;
    float* scores_out = out + NB * MAX_DET * 4;
    float* labels_out = out + NB * MAX_DET * 5;

    const int filled = M < MAX_DET ? M : MAX_DET;
    if (part == 0 && t >= filled && t < MAX_DET) {
        int base = img * MAX_DET + t;
        boxes_out[base * 4 + 0] = 0.0f;
        boxes_out[base * 4 + 1] = 0.0f;
        boxes_out[base * 4 + 2] = 0.0f;
        boxes_out[base * 4 + 3] = 0.0f;
        scores_out[base] = 0.0f;
        labels_out[base] = -1.0f;
    }

    const int entry = part * (C_THREADS / 32) + warp;
    if (entry < M) {
        unsigned long long mykey = s_keys[entry];   // warp-broadcast read
        int r = 0;
        for (int j = lane; j < M; j += 32)
            r += (s_keys[j] < mykey);
        #pragma unroll
        for (int o = 16; o; o >>= 1)
            r += __shfl_xor_sync(0xffffffffu, r, o);
        if (lane == 0 && r < MAX_DET) {
            int idx = (int)(mykey & 1023ULL);
            int g = img * NP + idx;
            float4 v = g_boxes[g];
            int base = img * MAX_DET + r;
            boxes_out[base * 4 + 0] = v.x;
            boxes_out[base * 4 + 1] = v.y;
            boxes_out[base * 4 + 2] = v.z;
            boxes_out[base * 4 + 3] = v.w;
            scores_out[base] = g_scores[g];
            labels_out[base] = (float)g_labels[g];
        }
    }
}

// ---------------- launch ----------------
extern "C" void kernel_launch(void* const* d_in, const int* in_sizes, int n_in,
                              void* d_out, int out_size) {
    const float* class_logits  = (const float*)d_in[0];
    const float* bbox_deltas   = (const float*)d_in[1];
    const float* roi_proposals = (const float*)d_in[2];
    const int*   image_sizes   = (const int*)d_in[3];
    float* out = (float*)d_out;

    zero_kernel<<<3, 512>>>();

    int total_warps = NB * NP;
    int threads = 256;
    int blocks = (total_warps * 32 + threads - 1) / threads;
    score_decode_kernel<<<blocks, threads>>>(class_logits, bbox_deltas,
                                             roi_proposals, image_sizes);

    int nmsWarps = NB * 90;
    int nmsBlocks = (nmsWarps * 32 + 255) / 256;
    nms_class_kernel<<<nmsBlocks, 256>>>();

    topk_rank_kernel<<<NB * C_PARTS, C_THREADS>>>(out);
}